// round 1
// baseline (speedup 1.0000x reference)
#include <cuda_runtime.h>
#include <cuda_bf16.h>
#include <math.h>

#define HH 100
#define WW 100
#define AA 9
#define NN (HH * WW * AA)          // 90000
#define PRE_K 6000
#define POST_K 300
#define CAND_CAP 16384
#define NBINS 65536
#define MIN_SIZE 0.02f
#define IOU_THR 0.7f
#define SUP_WORDS 188              // ceil(6000/32)

// ---------------- device scratch (no allocs allowed) ----------------
__device__ float              g_boxes[NN * 4];
__device__ unsigned long long g_keys[NN];
__device__ unsigned int       g_hist[NBINS];
__device__ unsigned long long g_cand[CAND_CAP];
__device__ int                g_cand_cnt;
__device__ unsigned int       g_thresh;

// ---------------- kernel 1: zero hist + counter ----------------
__global__ void zero_kernel() {
    int i = blockIdx.x * blockDim.x + threadIdx.x;
    if (i < NBINS) g_hist[i] = 0u;
    if (i == 0) g_cand_cnt = 0;
}

// ---------------- kernel 2: decode + score + key + histogram ----------------
__global__ void decode_kernel(const float* __restrict__ pred_cls,
                              const float* __restrict__ pred_reg,
                              const float* __restrict__ anchor) {
    int n = blockIdx.x * blockDim.x + threadIdx.x;
    if (n >= NN) return;

    float4 a = *(const float4*)&anchor[n * 4];     // x0 y0 x1 y1
    float4 r = *(const float4*)&pred_reg[n * 4];   // tx ty tw th

    float acx = (a.x + a.z) * 0.5f;
    float acy = (a.y + a.w) * 0.5f;
    float aw  = a.z - a.x;
    float ah  = a.w - a.y;

    float cx = r.x * aw + acx;
    float cy = r.y * ah + acy;
    float w  = __expf(r.z) == 0.f ? 0.f : expf(r.z) * aw;  // use expf (precise) below
    w = expf(r.z) * aw;
    float h = expf(r.w) * ah;

    float x0 = fminf(fmaxf(cx - w * 0.5f, 0.f), 1.f);
    float y0 = fminf(fmaxf(cy - h * 0.5f, 0.f), 1.f);
    float x1 = fminf(fmaxf(cx + w * 0.5f, 0.f), 1.f);
    float y1 = fminf(fmaxf(cy + h * 0.5f, 0.f), 1.f);

    float4 box = make_float4(x0, y0, x1, y1);
    *(float4*)&g_boxes[n * 4] = box;

    // softmax over the two logits, take class-1 prob
    float l0 = pred_cls[2 * n];
    float l1 = pred_cls[2 * n + 1];
    float m  = fmaxf(l0, l1);
    float e0 = expf(l0 - m);
    float e1 = expf(l1 - m);
    float p  = e1 / (e0 + e1);

    bool size_ok = ((y1 - y0) >= MIN_SIZE) && ((x1 - x0) >= MIN_SIZE);
    float s = size_ok ? p : -INFINITY;

    unsigned int ub = __float_as_uint(s);
    unsigned int ordered = (ub & 0x80000000u) ? ~ub : (ub | 0x80000000u);
    unsigned long long key =
        ((unsigned long long)ordered << 32) | (unsigned int)(~(unsigned int)n);
    g_keys[n] = key;

    atomicAdd(&g_hist[ordered >> 16], 1u);
}

// ---------------- kernel 3: find threshold bin (suffix count >= PRE_K) ----------------
__global__ void thresh_kernel() {
    __shared__ unsigned int part[1024];
    int t = threadIdx.x;
    unsigned int s = 0;
    int base = t * (NBINS / 1024);
    for (int b = 0; b < NBINS / 1024; b++) s += g_hist[base + b];
    part[t] = s;
    __syncthreads();
    if (t == 0) {
        unsigned int acc = 0;
        int pt = 1023;
        for (; pt >= 0; pt--) {
            if (acc + part[pt] >= (unsigned)PRE_K) break;
            acc += part[pt];
        }
        if (pt < 0) pt = 0;
        int lo = pt * (NBINS / 1024);
        int T  = lo;
        for (int b = lo + (NBINS / 1024) - 1; b >= lo; b--) {
            acc += g_hist[b];
            if (acc >= (unsigned)PRE_K) { T = b; break; }
        }
        g_thresh = (unsigned int)T;
    }
}

// ---------------- kernel 4: compact candidates ----------------
__global__ void compact_kernel() {
    int n = blockIdx.x * blockDim.x + threadIdx.x;
    if (n >= NN) return;
    unsigned long long key = g_keys[n];
    if ((unsigned int)(key >> 48) >= g_thresh) {
        int p = atomicAdd(&g_cand_cnt, 1);
        if (p < CAND_CAP) g_cand[p] = key;
    }
}

// ---------------- kernel 5: bitonic sort candidates (desc), write top 6000 back ----------------
__global__ void sort_kernel() {
    extern __shared__ unsigned long long sk[];
    int cnt = g_cand_cnt;
    if (cnt > CAND_CAP) cnt = CAND_CAP;
    for (int t = threadIdx.x; t < CAND_CAP; t += blockDim.x)
        sk[t] = (t < cnt) ? g_cand[t] : 0ULL;
    __syncthreads();
    for (int k = 2; k <= CAND_CAP; k <<= 1) {
        for (int j = k >> 1; j > 0; j >>= 1) {
            for (int t = threadIdx.x; t < CAND_CAP; t += blockDim.x) {
                int ixj = t ^ j;
                if (ixj > t) {
                    unsigned long long va = sk[t], vb = sk[ixj];
                    bool desc = ((t & k) == 0);
                    if (desc ? (va < vb) : (va > vb)) { sk[t] = vb; sk[ixj] = va; }
                }
            }
            __syncthreads();
        }
    }
    for (int t = threadIdx.x; t < PRE_K; t += blockDim.x) g_cand[t] = sk[t];
}

// ---------------- kernel 6: greedy NMS + write output ----------------
__global__ void nms_kernel(float* __restrict__ out) {
    extern __shared__ char smraw[];
    float4*       sBox   = (float4*)smraw;                       // 6000 * 16B
    float*        sArea  = (float*)(sBox + PRE_K);               // 6000 * 4B
    unsigned int* sValid = (unsigned int*)(sArea + PRE_K);       // 188 words
    unsigned int* sSup   = sValid + SUP_WORDS;                   // 188 words
    __shared__ int s_i;

    int tid = threadIdx.x, bd = blockDim.x;

    for (int w = tid; w < SUP_WORDS; w += bd) { sValid[w] = 0u; sSup[w] = 0u; }
    __syncthreads();

    for (int j = tid; j < PRE_K; j += bd) {
        unsigned long long key = g_cand[j];
        float4 b = make_float4(0.f, 0.f, 0.f, 0.f);
        if (key != 0ULL) {
            unsigned int idx = ~(unsigned int)key;
            if (idx < NN) b = *(const float4*)&g_boxes[idx * 4];
            if (key >> 63) atomicOr(&sValid[j >> 5], 1u << (j & 31));
        }
        sBox[j]  = b;
        sArea[j] = (b.z - b.x) * (b.w - b.y);
    }
    for (int t = tid; t < POST_K * 4; t += bd) out[t] = 0.f;
    __syncthreads();

    int kept = 0;   // authoritative in tid 0 only
    int pos  = 0;   // tid 0 scan position

    while (true) {
        if (tid == 0) {
            int i = -1;
            if (kept < POST_K) {
                int w = pos >> 5;
                if (w < SUP_WORDS) {
                    unsigned int m = (~sSup[w]) & sValid[w] &
                                     (0xFFFFFFFFu << (pos & 31));
                    while (true) {
                        if (m) { i = (w << 5) + __ffs(m) - 1; break; }
                        w++;
                        if (w >= SUP_WORDS) break;
                        m = (~sSup[w]) & sValid[w];
                    }
                }
                if (i >= PRE_K) i = -1;
            }
            s_i = i;
        }
        __syncthreads();
        int i = s_i;
        if (i < 0) break;

        float4 bi = sBox[i];
        float  ai = sArea[i];
        for (int j = i + 1 + tid; j < PRE_K; j += bd) {
            float4 bj = sBox[j];
            float x0 = fmaxf(bi.x, bj.x);
            float y0 = fmaxf(bi.y, bj.y);
            float x1 = fminf(bi.z, bj.z);
            float y1 = fminf(bi.w, bj.w);
            float iw = fmaxf(x1 - x0, 0.f);
            float ih = fmaxf(y1 - y0, 0.f);
            float inter = iw * ih;
            float uni   = ai + sArea[j] - inter;
            float iou   = inter / fmaxf(uni, 1e-12f);
            if (iou > IOU_THR) atomicOr(&sSup[j >> 5], 1u << (j & 31));
        }
        if (tid == 0) {
            out[kept * 4 + 0] = bi.x;
            out[kept * 4 + 1] = bi.y;
            out[kept * 4 + 2] = bi.z;
            out[kept * 4 + 3] = bi.w;
            kept++;
            pos = i + 1;
        }
        __syncthreads();
    }
}

// ---------------- launcher ----------------
extern "C" void kernel_launch(void* const* d_in, const int* in_sizes, int n_in,
                              void* d_out, int out_size) {
    const float* pred_cls = (const float*)d_in[0];
    const float* pred_reg = (const float*)d_in[1];
    const float* anchor   = (const float*)d_in[2];
    float* out = (float*)d_out;

    zero_kernel<<<(NBINS + 255) / 256, 256>>>();
    decode_kernel<<<(NN + 255) / 256, 256>>>(pred_cls, pred_reg, anchor);
    thresh_kernel<<<1, 1024>>>();
    compact_kernel<<<(NN + 255) / 256, 256>>>();

    size_t sort_smem = (size_t)CAND_CAP * sizeof(unsigned long long);      // 128 KB
    cudaFuncSetAttribute(sort_kernel, cudaFuncAttributeMaxDynamicSharedMemorySize,
                         (int)sort_smem);
    sort_kernel<<<1, 1024, sort_smem>>>();

    size_t nms_smem = (size_t)PRE_K * sizeof(float4) + (size_t)PRE_K * sizeof(float) +
                      2u * SUP_WORDS * sizeof(unsigned int);               // ~121.5 KB
    cudaFuncSetAttribute(nms_kernel, cudaFuncAttributeMaxDynamicSharedMemorySize,
                         (int)nms_smem);
    nms_kernel<<<1, 512, nms_smem>>>(out);
}

// round 3
// speedup vs baseline: 4.6603x; 4.6603x over previous
#include <cuda_runtime.h>
#include <cuda_bf16.h>
#include <math.h>

#define NN 90000
#define PRE_K 6000
#define POST_K 300
#define NW 188                   // ceil(6000/32)
#define NBINS 65536
#define CAND_CAP 8192
#define MIN_SIZE 0.02f

#define ST 512                   // sort threads
#define EPT (CAND_CAP / ST)      // 16 elems/thread
#define RBITS 5
#define RADIX 32
#define PASSES 10                // 50 bits >= 49-bit key

// ---------------- device scratch ----------------
__device__ unsigned long long g_keys[NN];
__device__ float4             g_boxes[NN];
__device__ unsigned int       g_hist[NBINS];
__device__ unsigned long long g_cand[CAND_CAP];
__device__ int                g_cand_cnt;
__device__ unsigned int       g_thresh;
__device__ float4             g_top[PRE_K + 32];
__device__ unsigned int       g_valid[NW];
__device__ unsigned int       g_maskT[NW * PRE_K];   // [word][row]

// padded counter index (avoids 32-way bank conflicts in the scan)
__device__ __forceinline__ int ci(int i) { return i + (i >> 5); }

// ---------------- kernel 0: zero hist + counter ----------------
__global__ void zero_kernel() {
    int i = blockIdx.x * blockDim.x + threadIdx.x;
    if (i < NBINS) g_hist[i] = 0u;
    if (i == 0) g_cand_cnt = 0;
}

// ---------------- kernel 1: decode + score + key + histogram ----------------
__global__ void decode_kernel(const float* __restrict__ pred_cls,
                              const float* __restrict__ pred_reg,
                              const float* __restrict__ anchor) {
    int n = blockIdx.x * blockDim.x + threadIdx.x;
    if (n >= NN) return;

    float4 a = *(const float4*)&anchor[n * 4];
    float4 r = *(const float4*)&pred_reg[n * 4];

    float acx = (a.x + a.z) * 0.5f;
    float acy = (a.y + a.w) * 0.5f;
    float aw  = a.z - a.x;
    float ah  = a.w - a.y;

    float cx = r.x * aw + acx;
    float cy = r.y * ah + acy;
    float w  = expf(r.z) * aw;
    float h  = expf(r.w) * ah;

    float x0 = fminf(fmaxf(cx - w * 0.5f, 0.f), 1.f);
    float y0 = fminf(fmaxf(cy - h * 0.5f, 0.f), 1.f);
    float x1 = fminf(fmaxf(cx + w * 0.5f, 0.f), 1.f);
    float y1 = fminf(fmaxf(cy + h * 0.5f, 0.f), 1.f);

    g_boxes[n] = make_float4(x0, y0, x1, y1);

    float l0 = pred_cls[2 * n];
    float l1 = pred_cls[2 * n + 1];
    float m  = fmaxf(l0, l1);
    float e0 = expf(l0 - m);
    float e1 = expf(l1 - m);
    float p  = e1 / (e0 + e1);

    bool size_ok = ((y1 - y0) >= MIN_SIZE) && ((x1 - x0) >= MIN_SIZE);
    float s = size_ok ? p : -INFINITY;

    unsigned int ub = __float_as_uint(s);
    unsigned int ordered = (ub & 0x80000000u) ? ~ub : (ub | 0x80000000u);
    // 49-bit key: ordered score (32b) << 17 | ~idx (17b)
    unsigned long long key =
        ((unsigned long long)ordered << 17) | ((~(unsigned int)n) & 0x1FFFFu);
    g_keys[n] = key;

    atomicAdd(&g_hist[ordered >> 16], 1u);
}

// ---------------- kernel 2: threshold bin (suffix count >= PRE_K) ----------------
__global__ void thresh_kernel() {
    __shared__ unsigned int part[1024];
    int t = threadIdx.x;
    unsigned int s = 0;
    int base = t * (NBINS / 1024);
    for (int b = 0; b < NBINS / 1024; b++) s += g_hist[base + b];
    part[t] = s;
    __syncthreads();
    if (t == 0) {
        unsigned int acc = 0;
        int pt = 1023;
        for (; pt >= 0; pt--) {
            if (acc + part[pt] >= (unsigned)PRE_K) break;
            acc += part[pt];
        }
        if (pt < 0) pt = 0;
        int lo = pt * (NBINS / 1024);
        int T  = lo;
        for (int b = lo + (NBINS / 1024) - 1; b >= lo; b--) {
            acc += g_hist[b];
            if (acc >= (unsigned)PRE_K) { T = b; break; }
        }
        g_thresh = (unsigned int)T;
    }
}

// ---------------- kernel 3: compact candidates ----------------
__global__ void compact_kernel() {
    int n = blockIdx.x * blockDim.x + threadIdx.x;
    if (n >= NN) return;
    unsigned long long key = g_keys[n];
    if ((unsigned int)(key >> 33) >= g_thresh) {     // bin = ordered >> 16
        int p = atomicAdd(&g_cand_cnt, 1);
        if (p < CAND_CAP) g_cand[p] = key;
    }
}

// ---------------- kernel 4: single-block LSD radix sort (stable, ascending) ----------------
__global__ void sort_kernel() {
    extern __shared__ char sm[];
    unsigned long long* bufA = (unsigned long long*)sm;
    unsigned long long* bufB = bufA + CAND_CAP;
    unsigned int* cnts = (unsigned int*)(bufB + CAND_CAP);  // ci(RADIX*ST) entries
    __shared__ unsigned int warp_sums[32];

    int tid  = threadIdx.x;
    int lane = tid & 31;
    int wid  = tid >> 5;
    int cnt  = g_cand_cnt;
    if (cnt > CAND_CAP) cnt = CAND_CAP;

    for (int i = tid; i < CAND_CAP; i += ST)
        bufA[i] = (i < cnt) ? g_cand[i] : 0ULL;
    __syncthreads();

    for (int pass = 0; pass < PASSES; pass++) {
        int shift = pass * RBITS;

        for (int i = tid; i < RADIX * ST; i += ST) cnts[ci(i)] = 0u;
        __syncthreads();

        // histogram over this thread's contiguous chunk
        unsigned long long keys[EPT];
        #pragma unroll
        for (int e = 0; e < EPT; e++) {
            keys[e] = bufA[tid * EPT + e];
            unsigned int d = (unsigned int)(keys[e] >> shift) & (RADIX - 1);
            cnts[ci(d * ST + tid)] += 1u;
        }
        __syncthreads();

        // exclusive scan of the RADIX*ST counters in linear (digit-major) order
        unsigned int local[RADIX];
        unsigned int sum = 0;
        #pragma unroll
        for (int k = 0; k < RADIX; k++) {
            local[k] = cnts[ci(tid * RADIX + k)];
            sum += local[k];
        }
        unsigned int pre = sum;
        #pragma unroll
        for (int o = 1; o < 32; o <<= 1) {
            unsigned int v = __shfl_up_sync(0xFFFFFFFFu, pre, o);
            if (lane >= o) pre += v;
        }
        unsigned int warp_total = __shfl_sync(0xFFFFFFFFu, pre, 31);
        unsigned int excl = pre - sum;
        if (lane == 31) warp_sums[wid] = warp_total;
        __syncthreads();
        if (wid == 0) {
            unsigned int v = (lane < ST / 32) ? warp_sums[lane] : 0u;
            unsigned int p = v;
            #pragma unroll
            for (int o = 1; o < 32; o <<= 1) {
                unsigned int x = __shfl_up_sync(0xFFFFFFFFu, p, o);
                if (lane >= o) p += x;
            }
            if (lane < ST / 32) warp_sums[lane] = p - v;
        }
        __syncthreads();
        unsigned int base = excl + warp_sums[wid];
        #pragma unroll
        for (int k = 0; k < RADIX; k++) {
            unsigned int c = local[k];
            cnts[ci(tid * RADIX + k)] = base;
            base += c;
        }
        __syncthreads();

        // stable scatter (chunk order within thread preserves stability)
        #pragma unroll
        for (int e = 0; e < EPT; e++) {
            unsigned int d   = (unsigned int)(keys[e] >> shift) & (RADIX - 1);
            int a            = ci(d * ST + tid);
            unsigned int pos = cnts[a];
            cnts[a]          = pos + 1u;
            bufB[pos]        = keys[e];
        }
        __syncthreads();

        unsigned long long* t = bufA; bufA = bufB; bufB = t;
    }

    // emit top PRE_K in descending order
    for (int r = tid; r < PRE_K; r += ST)
        g_cand[r] = bufA[CAND_CAP - 1 - r];
}

// ---------------- kernel 5: gather top boxes + validity bits ----------------
__global__ void gather_kernel() {
    int r = blockIdx.x * 128 + threadIdx.x;
    bool v = false;
    if (r < PRE_K) {
        unsigned long long key = g_cand[r];
        unsigned int idx = (~(unsigned int)key) & 0x1FFFFu;
        float4 b = (idx < NN) ? g_boxes[idx] : make_float4(0.f, 0.f, 0.f, 0.f);
        g_top[r] = b;
        v = (key >> 48) & 1ULL;     // score sign bit: valid iff score >= 0
    }
    unsigned int bal = __ballot_sync(0xFFFFFFFFu, v);
    if ((threadIdx.x & 31) == 0 && r < PRE_K) g_valid[r >> 5] = bal;
}

// ---------------- kernel 6: full suppression bitmask, transposed ----------------
__global__ void matrix_kernel() {
    __shared__ float4 cbox[32];
    __shared__ float  carea[32];
    int w   = blockIdx.y;
    int r0  = blockIdx.x * 128;
    int tid = threadIdx.x;

    if (tid < 32) {
        int c = w * 32 + tid;
        float4 b = (c < PRE_K) ? g_top[c] : make_float4(0.f, 0.f, 0.f, 0.f);
        cbox[tid]  = b;
        carea[tid] = (b.z - b.x) * (b.w - b.y);
    }
    __syncthreads();

    int r = r0 + tid;
    if (r >= PRE_K) return;

    unsigned int word = 0;
    int jbase = w * 32;
    if (jbase + 31 > r) {
        float4 bi = g_top[r];
        float  ai = (bi.z - bi.x) * (bi.w - bi.y);
        #pragma unroll
        for (int k = 0; k < 32; k++) {
            int j = jbase + k;
            float4 bj = cbox[k];
            float x0 = fmaxf(bi.x, bj.x);
            float y0 = fmaxf(bi.y, bj.y);
            float x1 = fminf(bi.z, bj.z);
            float y1 = fminf(bi.w, bj.w);
            float iw = fmaxf(x1 - x0, 0.f);
            float ih = fmaxf(y1 - y0, 0.f);
            float inter = iw * ih;
            float u     = ai + carea[k] - inter;
            float um    = fmaxf(u, 1e-12f);
            float t     = 0.7f * um;
            float d     = inter - t;
            bool sup;
            if (fabsf(d) <= 1e-5f * t)          // boundary band: exact division
                sup = (inter / um) > 0.7f;
            else
                sup = d > 0.f;
            if (sup && j > r && j < PRE_K) word |= (1u << k);
        }
    }
    g_maskT[w * PRE_K + r] = word;
}

// ---------------- kernel 7: chunked greedy serial scan ----------------
__global__ void serial_kernel(float* __restrict__ out) {
    __shared__ unsigned int sup[NW];
    __shared__ unsigned int svalid[NW];
    __shared__ unsigned int cm[32 * NW];
    __shared__ float4 sbox[32];

    int tid = threadIdx.x;                      // 256 threads
    for (int i = tid; i < NW; i += 256) { sup[i] = 0u; svalid[i] = g_valid[i]; }
    __syncthreads();

    int kept = 0;
    for (int c = 0; c * 32 < PRE_K && kept < POST_K; c++) {
        int r0 = c * 32;
        int rmax = min(32, PRE_K - r0);
        for (int idx = tid; idx < NW * 32; idx += 256) {
            int w  = idx >> 5;
            int rl = idx & 31;
            cm[rl * NW + w] = (rl < rmax) ? g_maskT[w * PRE_K + r0 + rl] : 0u;
        }
        if (tid < 32) sbox[tid] = (tid < rmax) ? g_top[r0 + tid]
                                               : make_float4(0.f, 0.f, 0.f, 0.f);
        __syncthreads();

        for (int rl = 0; rl < rmax; rl++) {
            int i = r0 + rl;
            bool keep = ((svalid[i >> 5] >> (i & 31)) & 1u) &&
                        !((sup[i >> 5] >> (i & 31)) & 1u);
            if (keep) {
                if (tid == 0) ((float4*)out)[kept] = sbox[rl];
                if (tid < NW) sup[tid] |= cm[rl * NW + tid];
                __syncthreads();
                kept++;
                if (kept >= POST_K) break;
            }
        }
        __syncthreads();
    }

    for (int idx = tid; idx < (POST_K - kept) * 4; idx += 256)
        out[kept * 4 + idx] = 0.f;
}

// ---------------- launcher ----------------
extern "C" void kernel_launch(void* const* d_in, const int* in_sizes, int n_in,
                              void* d_out, int out_size) {
    const float* pred_cls = (const float*)d_in[0];
    const float* pred_reg = (const float*)d_in[1];
    const float* anchor   = (const float*)d_in[2];
    float* out = (float*)d_out;

    zero_kernel<<<(NBINS + 255) / 256, 256>>>();
    decode_kernel<<<(NN + 255) / 256, 256>>>(pred_cls, pred_reg, anchor);
    thresh_kernel<<<1, 1024>>>();
    compact_kernel<<<(NN + 255) / 256, 256>>>();

    // sort smem: 2 key buffers + padded counters
    size_t sort_smem = 2u * CAND_CAP * sizeof(unsigned long long) +
                       (size_t)(RADIX * ST + (RADIX * ST) / 32 + 32) * sizeof(unsigned int);
    cudaFuncSetAttribute(sort_kernel, cudaFuncAttributeMaxDynamicSharedMemorySize,
                         (int)sort_smem);
    sort_kernel<<<1, ST, sort_smem>>>();

    gather_kernel<<<47, 128>>>();
    matrix_kernel<<<dim3(47, 188), 128>>>();
    serial_kernel<<<1, 256>>>(out);
}

// round 4
// speedup vs baseline: 6.2011x; 1.3306x over previous
#include <cuda_runtime.h>
#include <cuda_bf16.h>
#include <math.h>

#define NN 90000
#define PRE_K 6000
#define POST_K 300
#define NW 188                   // ceil(6000/32)
#define NBINS 65536
#define CAND_CAP 8192
#define MIN_SIZE 0.02f
#define NSEG 8                   // rank-kernel segments
#define SEG (CAND_CAP / NSEG)    // 1024 keys per segment

// ---------------- device scratch ----------------
__device__ unsigned long long g_keys[NN];
__device__ float4             g_boxes[NN];
__device__ unsigned int       g_hist[NBINS];
__device__ unsigned long long g_cand[CAND_CAP];
__device__ int                g_cand_cnt;
__device__ unsigned int       g_thresh;
__device__ int                g_rank[CAND_CAP];
__device__ float4             g_top[PRE_K + 32];
__device__ unsigned int       g_valid[NW];
__device__ unsigned int       g_maskT[NW * PRE_K];   // [word][row]

// ---------------- kernel 0: zero hist + rank + valid + counter ----------------
__global__ void zero_kernel() {
    int i = blockIdx.x * blockDim.x + threadIdx.x;
    if (i < NBINS) g_hist[i] = 0u;
    if (i < CAND_CAP) g_rank[i] = 0;
    if (i < NW) g_valid[i] = 0u;
    if (i == 0) g_cand_cnt = 0;
}

// ---------------- kernel 1: decode + score + key + histogram ----------------
__global__ void decode_kernel(const float* __restrict__ pred_cls,
                              const float* __restrict__ pred_reg,
                              const float* __restrict__ anchor) {
    int n = blockIdx.x * blockDim.x + threadIdx.x;
    if (n >= NN) return;

    float4 a = *(const float4*)&anchor[n * 4];
    float4 r = *(const float4*)&pred_reg[n * 4];

    float acx = (a.x + a.z) * 0.5f;
    float acy = (a.y + a.w) * 0.5f;
    float aw  = a.z - a.x;
    float ah  = a.w - a.y;

    float cx = r.x * aw + acx;
    float cy = r.y * ah + acy;
    float w  = expf(r.z) * aw;
    float h  = expf(r.w) * ah;

    float x0 = fminf(fmaxf(cx - w * 0.5f, 0.f), 1.f);
    float y0 = fminf(fmaxf(cy - h * 0.5f, 0.f), 1.f);
    float x1 = fminf(fmaxf(cx + w * 0.5f, 0.f), 1.f);
    float y1 = fminf(fmaxf(cy + h * 0.5f, 0.f), 1.f);

    g_boxes[n] = make_float4(x0, y0, x1, y1);

    float l0 = pred_cls[2 * n];
    float l1 = pred_cls[2 * n + 1];
    float m  = fmaxf(l0, l1);
    float e0 = expf(l0 - m);
    float e1 = expf(l1 - m);
    float p  = e1 / (e0 + e1);

    bool size_ok = ((y1 - y0) >= MIN_SIZE) && ((x1 - x0) >= MIN_SIZE);
    float s = size_ok ? p : -INFINITY;

    unsigned int ub = __float_as_uint(s);
    unsigned int ordered = (ub & 0x80000000u) ? ~ub : (ub | 0x80000000u);
    // 49-bit key: ordered score (32b) << 17 | ~idx (17b)  -> unique keys
    unsigned long long key =
        ((unsigned long long)ordered << 17) | ((~(unsigned int)n) & 0x1FFFFu);
    g_keys[n] = key;

    atomicAdd(&g_hist[ordered >> 16], 1u);
}

// ---------------- kernel 2: threshold bin (suffix count >= PRE_K) ----------------
__global__ void thresh_kernel() {
    __shared__ unsigned int part[1024];
    int t = threadIdx.x;
    unsigned int s = 0;
    int base = t * (NBINS / 1024);
    for (int b = 0; b < NBINS / 1024; b++) s += g_hist[base + b];
    part[t] = s;
    __syncthreads();
    if (t == 0) {
        unsigned int acc = 0;
        int pt = 1023;
        for (; pt >= 0; pt--) {
            if (acc + part[pt] >= (unsigned)PRE_K) break;
            acc += part[pt];
        }
        if (pt < 0) pt = 0;
        int lo = pt * (NBINS / 1024);
        int T  = lo;
        for (int b = lo + (NBINS / 1024) - 1; b >= lo; b--) {
            acc += g_hist[b];
            if (acc >= (unsigned)PRE_K) { T = b; break; }
        }
        g_thresh = (unsigned int)T;
    }
}

// ---------------- kernel 3: compact candidates ----------------
__global__ void compact_kernel() {
    int n = blockIdx.x * blockDim.x + threadIdx.x;
    if (n >= NN) return;
    unsigned long long key = g_keys[n];
    if ((unsigned int)(key >> 33) >= g_thresh) {     // bin = ordered >> 16
        int p = atomicAdd(&g_cand_cnt, 1);
        if (p < CAND_CAP) g_cand[p] = key;
    }
}

// ---------------- kernel 4: rank by counting (keys unique -> exact order) ----
// grid (32, NSEG), block 256.  block (bx, s): candidates bx*256..+255 counted
// against segment s of the key array; partial counts atomicAdd'ed.
__global__ void rank_kernel() {
    __shared__ unsigned long long tile[256];
    int tid = threadIdx.x;
    int c   = blockIdx.x * 256 + tid;
    int C   = g_cand_cnt; if (C > CAND_CAP) C = CAND_CAP;

    unsigned long long kc = (c < C) ? g_cand[c] : 0xFFFFFFFFFFFFFFFFULL;

    int seg0 = blockIdx.y * SEG;
    int cnt  = 0;
    for (int t0 = seg0; t0 < seg0 + SEG; t0 += 256) {
        int gi = t0 + tid;
        tile[tid] = (gi < C) ? g_cand[gi] : 0ULL;    // 0 never > any candidate key
        __syncthreads();
        #pragma unroll 8
        for (int k = 0; k < 256; k++)
            cnt += (tile[k] > kc);
        __syncthreads();
    }
    if (c < C && cnt) atomicAdd(&g_rank[c], cnt);
}

// ---------------- kernel 5: scatter into sorted order + validity ------------
__global__ void scatter_kernel() {
    int c = blockIdx.x * 256 + threadIdx.x;
    int C = g_cand_cnt; if (C > CAND_CAP) C = CAND_CAP;
    if (c >= C) return;
    int rank = g_rank[c];
    if (rank >= PRE_K) return;
    unsigned long long key = g_cand[c];
    unsigned int idx = (~(unsigned int)key) & 0x1FFFFu;
    float4 b = (idx < NN) ? g_boxes[idx] : make_float4(0.f, 0.f, 0.f, 0.f);
    g_top[rank] = b;
    if ((key >> 48) & 1ULL)                          // score sign: valid iff >= 0
        atomicOr(&g_valid[rank >> 5], 1u << (rank & 31));
}

// ---------------- kernel 6: suppression bitmask (upper triangle only) -------
__global__ void matrix_kernel() {
    __shared__ float4 cbox[32];
    __shared__ float  carea[32];
    int w   = blockIdx.y;
    int r0  = blockIdx.x * 128;
    int jbase = w * 32;
    if (jbase + 31 <= r0) return;                    // whole block below diagonal

    int tid = threadIdx.x;
    if (tid < 32) {
        int cc = jbase + tid;
        float4 b = (cc < PRE_K) ? g_top[cc] : make_float4(0.f, 0.f, 0.f, 0.f);
        cbox[tid]  = b;
        carea[tid] = (b.z - b.x) * (b.w - b.y);
    }
    __syncthreads();

    int r = r0 + tid;
    if (r >= PRE_K) return;
    if (jbase + 31 <= r) return;                     // row's word all zero: .bss stands

    float4 bi = g_top[r];
    float  ai = (bi.z - bi.x) * (bi.w - bi.y);
    unsigned int word = 0;
    #pragma unroll
    for (int k = 0; k < 32; k++) {
        int j = jbase + k;
        float4 bj = cbox[k];
        float x0 = fmaxf(bi.x, bj.x);
        float y0 = fmaxf(bi.y, bj.y);
        float x1 = fminf(bi.z, bj.z);
        float y1 = fminf(bi.w, bj.w);
        float iw = fmaxf(x1 - x0, 0.f);
        float ih = fmaxf(y1 - y0, 0.f);
        float inter = iw * ih;
        float u     = ai + carea[k] - inter;
        float um    = fmaxf(u, 1e-12f);
        float t     = 0.7f * um;
        float d     = inter - t;
        bool sup;
        if (fabsf(d) <= 1e-5f * t)                   // boundary band: exact division
            sup = (inter / um) > 0.7f;
        else
            sup = d > 0.f;
        if (sup && j > r && j < PRE_K) word |= (1u << k);
    }
    g_maskT[w * PRE_K + r] = word;
}

// ---------------- kernel 7: chunked greedy serial scan ----------------------
__global__ void serial_kernel(float* __restrict__ out) {
    __shared__ unsigned int sup[NW];
    __shared__ unsigned int svalid[NW];
    __shared__ unsigned int cm[32 * NW];
    __shared__ float4 sbox[32];

    int tid = threadIdx.x;                           // 256 threads
    for (int i = tid; i < NW; i += 256) { sup[i] = 0u; svalid[i] = g_valid[i]; }
    __syncthreads();

    int kept = 0;
    for (int c = 0; c * 32 < PRE_K && kept < POST_K; c++) {
        int r0 = c * 32;
        int rmax = min(32, PRE_K - r0);
        for (int idx = tid; idx < NW * 32; idx += 256) {
            int w  = idx >> 5;
            int rl = idx & 31;
            // rows below the diagonal within this chunk read zero words anyway
            cm[rl * NW + w] = (rl < rmax) ? g_maskT[w * PRE_K + r0 + rl] : 0u;
        }
        if (tid < 32) sbox[tid] = (tid < rmax) ? g_top[r0 + tid]
                                               : make_float4(0.f, 0.f, 0.f, 0.f);
        __syncthreads();

        for (int rl = 0; rl < rmax; rl++) {
            int i = r0 + rl;
            bool keep = ((svalid[i >> 5] >> (i & 31)) & 1u) &&
                        !((sup[i >> 5] >> (i & 31)) & 1u);
            if (keep) {
                if (tid == 0) ((float4*)out)[kept] = sbox[rl];
                if (tid < NW) sup[tid] |= cm[rl * NW + tid];
                __syncthreads();
                kept++;
                if (kept >= POST_K) break;
            }
        }
        __syncthreads();
    }

    for (int idx = tid; idx < (POST_K - kept) * 4; idx += 256)
        out[kept * 4 + idx] = 0.f;
}

// ---------------- launcher ----------------
extern "C" void kernel_launch(void* const* d_in, const int* in_sizes, int n_in,
                              void* d_out, int out_size) {
    const float* pred_cls = (const float*)d_in[0];
    const float* pred_reg = (const float*)d_in[1];
    const float* anchor   = (const float*)d_in[2];
    float* out = (float*)d_out;

    zero_kernel<<<NBINS / 256, 256>>>();
    decode_kernel<<<(NN + 255) / 256, 256>>>(pred_cls, pred_reg, anchor);
    thresh_kernel<<<1, 1024>>>();
    compact_kernel<<<(NN + 255) / 256, 256>>>();
    rank_kernel<<<dim3(CAND_CAP / 256, NSEG), 256>>>();
    scatter_kernel<<<CAND_CAP / 256, 256>>>();
    matrix_kernel<<<dim3(47, 188), 128>>>();
    serial_kernel<<<1, 256>>>(out);
}